// round 2
// baseline (speedup 1.0000x reference)
#include <cuda_runtime.h>
#include <cuda_bf16.h>

#define N_NODES 100000
#define N_EDGES 1000000
#define DIM 64
#define EDIM 16

// Flag: 1 if edge_index is int64, 0 if int32. Set by detect_kernel each launch.
__device__ int g_idx_is64;

// ---------------------------------------------------------------------------
// Kernel 0: detect index dtype. int64 little-endian node ids < 100000 have all
// high 32-bit words zero; genuine int32 data has nonzero odd-position words.
// ---------------------------------------------------------------------------
__global__ void detect_kernel(const unsigned int* __restrict__ w) {
    if (threadIdx.x == 0) {
        int is64 = 1;
        for (int i = 1; i < 1024; i += 2)
            if (w[i] != 0u) { is64 = 0; break; }
        g_idx_is64 = is64;
    }
}

// ---------------------------------------------------------------------------
// Kernel 1: zero the output buffer (used as the scatter-sum accumulator)
// ---------------------------------------------------------------------------
__global__ void zero_kernel(float4* __restrict__ out, int n4) {
    int i = blockIdx.x * blockDim.x + threadIdx.x;
    if (i < n4) out[i] = make_float4(0.f, 0.f, 0.f, 0.f);
}

// ---------------------------------------------------------------------------
// Kernel 2: per-edge message + scatter
//   msg = relu(x[src] + edge_attr @ We + be); aggr[dst] += msg  (vec2 atomics)
// One warp per edge. Lane handles output cols (2*lane, 2*lane+1).
// ---------------------------------------------------------------------------
__global__ __launch_bounds__(256) void edge_kernel(
    const float* __restrict__ x,
    const void* __restrict__ ei_raw,
    const float* __restrict__ ea,
    const float* __restrict__ We,
    const float* __restrict__ be,
    float* __restrict__ aggr)
{
    __shared__ float2 Wes[EDIM * 32];   // We verbatim as float2 pairs: 4 KB

    int tid = threadIdx.x;
    for (int i = tid; i < EDIM * 32; i += blockDim.x)
        Wes[i] = ((const float2*)We)[i];
    __syncthreads();

    int e    = (blockIdx.x * blockDim.x + tid) >> 5;
    int lane = tid & 31;
    if (e >= N_EDGES) return;

    int src, dst;
    if (g_idx_is64) {
        const long long* ei = (const long long*)ei_raw;
        src = (int)ei[e];
        dst = (int)ei[N_EDGES + e];
    } else {
        const int* ei = (const int*)ei_raw;
        src = ei[e];
        dst = ei[N_EDGES + e];
    }

    // edge_attr row: lanes 0..15 hold one value each, broadcast via shuffle
    float eav = (lane < EDIM) ? ea[(long long)e * EDIM + lane] : 0.f;

    float2 acc = ((const float2*)be)[lane];
#pragma unroll
    for (int k = 0; k < EDIM; k++) {
        float a  = __shfl_sync(0xffffffffu, eav, k);
        float2 w = Wes[k * 32 + lane];
        acc.x += a * w.x;
        acc.y += a * w.y;
    }

    float2 xv = ((const float2*)x)[(long long)src * 32 + lane];
    acc.x = fmaxf(acc.x + xv.x, 0.f);
    acc.y = fmaxf(acc.y + xv.y, 0.f);

    float* p = aggr + (long long)dst * DIM + lane * 2;
    asm volatile("red.global.add.v2.f32 [%0], {%1, %2};"
                 :: "l"(p), "f"(acc.x), "f"(acc.y) : "memory");
}

// ---------------------------------------------------------------------------
// Kernel 3: per-node epilogue
//   h0 = x + aggr;  h1 = relu(h0@W1 + b1);  h2 = h1@W2 + b2;
//   out = relu(LN(h2))
// 2 nodes per warp (amortizes shared-weight reads), 4 warps per block.
// Lane owns output cols (2*lane, 2*lane+1) of both nodes.
// ---------------------------------------------------------------------------
__global__ __launch_bounds__(128) void node_kernel(
    const float* __restrict__ x,
    const float* __restrict__ W1,
    const float* __restrict__ b1,
    const float* __restrict__ W2,
    const float* __restrict__ b2,
    const float* __restrict__ gamma,
    const float* __restrict__ beta,
    float* __restrict__ out)     // holds aggr on entry; overwritten in place
{
    __shared__ float2 W1s[DIM * 32];    // 16 KB
    __shared__ float2 W2s[DIM * 32];    // 16 KB
    __shared__ float  hs[4][2 * DIM];   // per-warp h for 2 nodes

    int tid = threadIdx.x;
    for (int i = tid; i < DIM * 32; i += 128) {
        W1s[i] = ((const float2*)W1)[i];
        W2s[i] = ((const float2*)W2)[i];
    }
    __syncthreads();

    int w = tid >> 5, lane = tid & 31;
    int n0 = (blockIdx.x * 4 + w) * 2;          // this warp's pair of nodes
    if (n0 >= N_NODES) return;
    float* h = hs[w];

    // h0 = x + aggr
    {
        float2 xa = ((const float2*)x)[(long long)n0 * 32 + lane];
        float2 ga = ((const float2*)out)[(long long)n0 * 32 + lane];
        h[2 * lane]     = xa.x + ga.x;
        h[2 * lane + 1] = xa.y + ga.y;
        float2 xb = ((const float2*)x)[(long long)(n0 + 1) * 32 + lane];
        float2 gb = ((const float2*)out)[(long long)(n0 + 1) * 32 + lane];
        h[DIM + 2 * lane]     = xb.x + gb.x;
        h[DIM + 2 * lane + 1] = xb.y + gb.y;
    }
    __syncwarp();

    // layer 1
    float2 b1p = ((const float2*)b1)[lane];
    float2 a0 = b1p, a1 = b1p;
#pragma unroll
    for (int k = 0; k < DIM; k++) {
        float2 wv = W1s[k * 32 + lane];
        float ha = h[k], hb = h[DIM + k];
        a0.x += ha * wv.x;  a0.y += ha * wv.y;
        a1.x += hb * wv.x;  a1.y += hb * wv.y;
    }
    __syncwarp();   // all h reads done before overwrite
    h[2 * lane]           = fmaxf(a0.x, 0.f);
    h[2 * lane + 1]       = fmaxf(a0.y, 0.f);
    h[DIM + 2 * lane]     = fmaxf(a1.x, 0.f);
    h[DIM + 2 * lane + 1] = fmaxf(a1.y, 0.f);
    __syncwarp();

    // layer 2
    float2 b2p = ((const float2*)b2)[lane];
    a0 = b2p; a1 = b2p;
#pragma unroll
    for (int k = 0; k < DIM; k++) {
        float2 wv = W2s[k * 32 + lane];
        float ha = h[k], hb = h[DIM + k];
        a0.x += ha * wv.x;  a0.y += ha * wv.y;
        a1.x += hb * wv.x;  a1.y += hb * wv.y;
    }

    // LayerNorm + ReLU (warp-reduce over 64 vals, 2 per lane per node)
    float s0 = a0.x + a0.y, q0 = a0.x * a0.x + a0.y * a0.y;
    float s1 = a1.x + a1.y, q1 = a1.x * a1.x + a1.y * a1.y;
#pragma unroll
    for (int o = 16; o > 0; o >>= 1) {
        s0 += __shfl_xor_sync(0xffffffffu, s0, o);
        q0 += __shfl_xor_sync(0xffffffffu, q0, o);
        s1 += __shfl_xor_sync(0xffffffffu, s1, o);
        q1 += __shfl_xor_sync(0xffffffffu, q1, o);
    }
    const float inv = 1.0f / DIM;
    float mu0 = s0 * inv, var0 = fmaxf(q0 * inv - mu0 * mu0, 0.f);
    float mu1 = s1 * inv, var1 = fmaxf(q1 * inv - mu1 * mu1, 0.f);
    float r0 = rsqrtf(var0 + 1e-5f);
    float r1 = rsqrtf(var1 + 1e-5f);

    float2 g  = ((const float2*)gamma)[lane];
    float2 bb = ((const float2*)beta)[lane];

    float2 o0, o1;
    o0.x = fmaxf((a0.x - mu0) * r0 * g.x + bb.x, 0.f);
    o0.y = fmaxf((a0.y - mu0) * r0 * g.y + bb.y, 0.f);
    o1.x = fmaxf((a1.x - mu1) * r1 * g.x + bb.x, 0.f);
    o1.y = fmaxf((a1.y - mu1) * r1 * g.y + bb.y, 0.f);

    ((float2*)out)[(long long)n0 * 32 + lane]       = o0;
    ((float2*)out)[(long long)(n0 + 1) * 32 + lane] = o1;
}

// ---------------------------------------------------------------------------
// Launch
// ---------------------------------------------------------------------------
extern "C" void kernel_launch(void* const* d_in, const int* in_sizes, int n_in,
                              void* d_out, int out_size) {
    const float* x     = (const float*)d_in[0];
    const void*  ei    = d_in[1];
    const float* ea    = (const float*)d_in[2];
    const float* We    = (const float*)d_in[3];
    const float* be    = (const float*)d_in[4];
    const float* W1    = (const float*)d_in[5];
    const float* b1    = (const float*)d_in[6];
    const float* W2    = (const float*)d_in[7];
    const float* b2    = (const float*)d_in[8];
    const float* gamma = (const float*)d_in[9];
    const float* beta  = (const float*)d_in[10];
    float* out = (float*)d_out;

    // 0) detect edge_index dtype (int32 vs int64)
    detect_kernel<<<1, 32>>>((const unsigned int*)ei);

    // 1) zero accumulator (d_out doubles as aggr buffer)
    int n4 = N_NODES * DIM / 4;
    zero_kernel<<<(n4 + 255) / 256, 256>>>((float4*)out, n4);

    // 2) edge messages + scatter (warp per edge, 8 warps/block)
    int edge_blocks = (N_EDGES + 7) / 8;
    edge_kernel<<<edge_blocks, 256>>>(x, ei, ea, We, be, out);

    // 3) node MLP + LayerNorm (2 nodes/warp, 4 warps/block -> 8 nodes/block)
    int node_blocks = (N_NODES + 7) / 8;
    node_kernel<<<node_blocks, 128>>>(x, W1, b1, W2, b2, gamma, beta, out);
}

// round 3
// speedup vs baseline: 1.6157x; 1.6157x over previous
#include <cuda_runtime.h>
#include <cuda_bf16.h>

#define N_NODES 100000
#define N_EDGES 1000000
#define DIM 64
#define EDIM 16

// Flag: 1 if edge_index is int64, 0 if int32. Set by detect_kernel each launch.
__device__ int g_idx_is64;

// ---------------------------------------------------------------------------
// packed fp32x2 helpers (Blackwell FFMA2)
// ---------------------------------------------------------------------------
__device__ __forceinline__ unsigned long long f2_as_u64(float a, float b) {
    unsigned long long r;
    asm("mov.b64 %0, {%1, %2};" : "=l"(r) : "f"(a), "f"(b));
    return r;
}
__device__ __forceinline__ void u64_as_f2(unsigned long long v, float& a, float& b) {
    asm("mov.b64 {%0, %1}, %2;" : "=f"(a), "=f"(b) : "l"(v));
}
__device__ __forceinline__ void ffma2(unsigned long long& d,
                                      unsigned long long a, unsigned long long b) {
    asm("fma.rn.f32x2 %0, %1, %2, %0;" : "+l"(d) : "l"(a), "l"(b));
}

// ---------------------------------------------------------------------------
// Kernel 0: detect index dtype (parallel). int64 node ids < 100000 have all
// high 32-bit words zero.
// ---------------------------------------------------------------------------
__global__ void detect_kernel(const unsigned int* __restrict__ w) {
    __shared__ unsigned int nz[8];
    unsigned int v = w[2 * threadIdx.x + 1];
    unsigned int any = __ballot_sync(0xffffffffu, v != 0u);
    if ((threadIdx.x & 31) == 0) nz[threadIdx.x >> 5] = any;
    __syncthreads();
    if (threadIdx.x == 0) {
        unsigned int a = 0;
#pragma unroll
        for (int i = 0; i < 8; i++) a |= nz[i];
        g_idx_is64 = (a == 0u) ? 1 : 0;
    }
}

// ---------------------------------------------------------------------------
// Kernel 1: zero the output buffer (used as the scatter-sum accumulator)
// ---------------------------------------------------------------------------
__global__ void zero_kernel(float4* __restrict__ out, int n4) {
    int i = blockIdx.x * blockDim.x + threadIdx.x;
    if (i < n4) out[i] = make_float4(0.f, 0.f, 0.f, 0.f);
}

// ---------------------------------------------------------------------------
// Kernel 2: per-edge message + scatter.  Two edges per warp, 16 lanes/edge,
// lane owns 4 output cols, red.global.add.v4.f32 (16 atomics/edge).
// ---------------------------------------------------------------------------
__global__ __launch_bounds__(256) void edge_kernel(
    const float4* __restrict__ x4,
    const void* __restrict__ ei_raw,
    const float* __restrict__ ea,
    const float4* __restrict__ We4,
    const float4* __restrict__ be4,
    float* __restrict__ aggr)
{
    __shared__ float4 Wes[EDIM * 16];   // 4 KB, row k as 16 float4

    int tid = threadIdx.x;
    for (int i = tid; i < EDIM * 16; i += 256) Wes[i] = We4[i];
    __syncthreads();

    int gw   = blockIdx.x * 8 + (tid >> 5);
    int lane = tid & 31;
    int half = lane >> 4, l = lane & 15;
    int e = gw * 2 + half;              // grid sized exactly: no tail check

    int src, dst;
    if (g_idx_is64) {
        const long long* ei = (const long long*)ei_raw;
        src = (int)__ldcs(&ei[e]);
        dst = (int)__ldcs(&ei[N_EDGES + e]);
    } else {
        const int* ei = (const int*)ei_raw;
        src = __ldcs(&ei[e]);
        dst = __ldcs(&ei[N_EDGES + e]);
    }

    // 16 lanes hold one edge_attr value each (streaming load: don't pollute L2)
    float eav = __ldcs(&ea[e * EDIM + l]);

    float4 acc = be4[l];
#pragma unroll
    for (int k = 0; k < EDIM; k++) {
        float a  = __shfl_sync(0xffffffffu, eav, (half << 4) | k);
        float4 w = Wes[k * 16 + l];
        acc.x += a * w.x; acc.y += a * w.y;
        acc.z += a * w.z; acc.w += a * w.w;
    }

    float4 xv = x4[src * 16 + l];
    acc.x = fmaxf(acc.x + xv.x, 0.f);
    acc.y = fmaxf(acc.y + xv.y, 0.f);
    acc.z = fmaxf(acc.z + xv.z, 0.f);
    acc.w = fmaxf(acc.w + xv.w, 0.f);

    float* p = aggr + (size_t)dst * DIM + l * 4;
    asm volatile("red.global.add.v4.f32 [%0], {%1,%2,%3,%4};"
                 :: "l"(p), "f"(acc.x), "f"(acc.y), "f"(acc.z), "f"(acc.w)
                 : "memory");
}

// ---------------------------------------------------------------------------
// Kernel 3: per-node epilogue. 8 nodes/warp, 8 warps/block (64 nodes/block).
// Weights stored pre-paired by k: Wp[k2][c] = (W[2k2][c], W[2k2+1][c]) packed
// 64-bit, so the dot product runs on fma.rn.f32x2 with interleaved partial
// sums (horizontal add at the end).
// ---------------------------------------------------------------------------
#define NPW 8
__global__ __launch_bounds__(256, 4) void node_kernel(
    const float2* __restrict__ x,
    const float* __restrict__ W1,
    const float* __restrict__ b1,
    const float* __restrict__ W2,
    const float* __restrict__ b2,
    const float* __restrict__ gamma,
    const float* __restrict__ beta,
    float2* __restrict__ out)     // holds aggr on entry; overwritten in place
{
    __shared__ unsigned long long W1p[32 * 64];   // 16 KB
    __shared__ unsigned long long W2p[32 * 64];   // 16 KB
    __shared__ float hs[8][NPW * DIM];            // 16 KB

    int tid = threadIdx.x;
    for (int i = tid; i < 32 * 64; i += 256) {
        int k2 = i >> 6, c = i & 63;
        W1p[i] = f2_as_u64(W1[(2 * k2) * 64 + c], W1[(2 * k2 + 1) * 64 + c]);
        W2p[i] = f2_as_u64(W2[(2 * k2) * 64 + c], W2[(2 * k2 + 1) * 64 + c]);
    }
    __syncthreads();

    int w = tid >> 5, lane = tid & 31;
    int base = (blockIdx.x * 8 + w) * NPW;
    if (base >= N_NODES) return;
    float* h = hs[w];

    // h = x + aggr
#pragma unroll
    for (int n = 0; n < NPW; n++) {
        int node = base + n;
        if (node < N_NODES) {
            float2 xv = x[(size_t)node * 32 + lane];
            float2 av = out[(size_t)node * 32 + lane];
            *(float2*)&h[n * DIM + 2 * lane] = make_float2(xv.x + av.x, xv.y + av.y);
        }
    }
    __syncwarp();

    unsigned long long accA[NPW], accB[NPW];

    // ---- layer 1 ----
    {
        float bA = b1[2 * lane], bB = b1[2 * lane + 1];
#pragma unroll
        for (int n = 0; n < NPW; n++) {
            accA[n] = f2_as_u64(bA, 0.f);
            accB[n] = f2_as_u64(bB, 0.f);
        }
    }
#pragma unroll
    for (int k2 = 0; k2 < 32; k2++) {
        ulonglong2 wp = *(const ulonglong2*)&W1p[k2 * 64 + 2 * lane];
#pragma unroll
        for (int n = 0; n < NPW; n++) {
            unsigned long long h2 = *(const unsigned long long*)&h[n * DIM + 2 * k2];
            ffma2(accA[n], h2, wp.x);
            ffma2(accB[n], h2, wp.y);
        }
    }
    __syncwarp();   // all h reads done before overwrite
#pragma unroll
    for (int n = 0; n < NPW; n++) {
        float ax, ay, bx, by;
        u64_as_f2(accA[n], ax, ay);
        u64_as_f2(accB[n], bx, by);
        *(float2*)&h[n * DIM + 2 * lane] =
            make_float2(fmaxf(ax + ay, 0.f), fmaxf(bx + by, 0.f));
    }
    __syncwarp();

    // ---- layer 2 ----
    {
        float bA = b2[2 * lane], bB = b2[2 * lane + 1];
#pragma unroll
        for (int n = 0; n < NPW; n++) {
            accA[n] = f2_as_u64(bA, 0.f);
            accB[n] = f2_as_u64(bB, 0.f);
        }
    }
#pragma unroll
    for (int k2 = 0; k2 < 32; k2++) {
        ulonglong2 wp = *(const ulonglong2*)&W2p[k2 * 64 + 2 * lane];
#pragma unroll
        for (int n = 0; n < NPW; n++) {
            unsigned long long h2 = *(const unsigned long long*)&h[n * DIM + 2 * k2];
            ffma2(accA[n], h2, wp.x);
            ffma2(accB[n], h2, wp.y);
        }
    }

    // ---- LayerNorm + ReLU ----
    float2 g  = make_float2(gamma[2 * lane], gamma[2 * lane + 1]);
    float2 bt = make_float2(beta[2 * lane],  beta[2 * lane + 1]);
    const float inv = 1.0f / DIM;

#pragma unroll
    for (int n = 0; n < NPW; n++) {
        float ax, ay, bx, by;
        u64_as_f2(accA[n], ax, ay);
        u64_as_f2(accB[n], bx, by);
        float v0 = ax + ay, v1 = bx + by;
        float s = v0 + v1, q = v0 * v0 + v1 * v1;
#pragma unroll
        for (int o = 16; o > 0; o >>= 1) {
            s += __shfl_xor_sync(0xffffffffu, s, o);
            q += __shfl_xor_sync(0xffffffffu, q, o);
        }
        float mu  = s * inv;
        float var = fmaxf(q * inv - mu * mu, 0.f);
        float r   = rsqrtf(var + 1e-5f);
        int node = base + n;
        if (node < N_NODES) {
            float2 o2;
            o2.x = fmaxf((v0 - mu) * r * g.x + bt.x, 0.f);
            o2.y = fmaxf((v1 - mu) * r * g.y + bt.y, 0.f);
            out[(size_t)node * 32 + lane] = o2;
        }
    }
}

// ---------------------------------------------------------------------------
// Launch
// ---------------------------------------------------------------------------
extern "C" void kernel_launch(void* const* d_in, const int* in_sizes, int n_in,
                              void* d_out, int out_size) {
    const float* x     = (const float*)d_in[0];
    const void*  ei    = d_in[1];
    const float* ea    = (const float*)d_in[2];
    const float* We    = (const float*)d_in[3];
    const float* be    = (const float*)d_in[4];
    const float* W1    = (const float*)d_in[5];
    const float* b1    = (const float*)d_in[6];
    const float* W2    = (const float*)d_in[7];
    const float* b2    = (const float*)d_in[8];
    const float* gamma = (const float*)d_in[9];
    const float* beta  = (const float*)d_in[10];
    float* out = (float*)d_out;

    // 0) detect edge_index dtype (int32 vs int64)
    detect_kernel<<<1, 256>>>((const unsigned int*)ei);

    // 1) zero accumulator (d_out doubles as aggr buffer)
    int n4 = N_NODES * DIM / 4;
    zero_kernel<<<(n4 + 255) / 256, 256>>>((float4*)out, n4);

    // 2) edge messages + scatter: 16 edges/block, exact grid
    edge_kernel<<<N_EDGES / 16, 256>>>((const float4*)x, ei, ea,
                                       (const float4*)We, (const float4*)be, out);

    // 3) node MLP + LayerNorm: 64 nodes/block
    node_kernel<<<(N_NODES + 63) / 64, 256>>>((const float2*)x, W1, b1, W2, b2,
                                              gamma, beta, (float2*)out);
}